// round 13
// baseline (speedup 1.0000x reference)
#include <cuda_runtime.h>
#include <math.h>

#define T_SEQ 2048
#define H     768
#define H3    2304
#define NL    10
#define NIN   384
#define NOUT  384

#define NBR 48                // CTAs per role (3 roles -> 144 CTAs, 1/SM)
#define NW  16                // warps (h elements) per CTA
#define THR 512
#define CANARY 0x7FC0DEADu    // quiet-NaN payload; unreachable by GRU math

// ---------------- scratch (no allocation allowed) ----------------
__device__ float g_gi0[T_SEQ * H3];     // even-layer gi (GEMM output, plain)
__device__ float g_gi1[T_SEQ * H3];     // odd-layer gi (streamed, canary)
__device__ float g_hl[NL][T_SEQ][H];    // per-layer h outputs (canary)

__global__ void reset_h_kernel() {
    unsigned* p = (unsigned*)g_hl;
    const size_t n = (size_t)NL * T_SEQ * H;
    for (size_t i = blockIdx.x * blockDim.x + threadIdx.x; i < n;
         i += (size_t)gridDim.x * blockDim.x)
        p[i] = CANARY;
}
__global__ void reset_gi1_kernel() {
    unsigned* p = (unsigned*)g_gi1;
    const size_t n = (size_t)T_SEQ * H3;
    for (size_t i = blockIdx.x * blockDim.x + threadIdx.x; i < n;
         i += (size_t)gridDim.x * blockDim.x)
        p[i] = CANARY;
}

// ---------------- GEMM: C[M,N] = A[M,K] * B[N,K]^T + bias[N] ----------------
__global__ void __launch_bounds__(256) gemm_nt_bias_kernel(
    const float* __restrict__ A, const float* __restrict__ B,
    const float* __restrict__ bias, float* __restrict__ C,
    int M, int N, int K)
{
    __shared__ float As[8][128];
    __shared__ float Bs[8][132];

    const int tid = threadIdx.x;
    const int bm = blockIdx.y * 128;
    const int bn = blockIdx.x * 128;
    const int m0 = (tid >> 4) * 8;
    const int n0 = (tid & 15) * 8;

    float acc[8][8];
#pragma unroll
    for (int i = 0; i < 8; i++)
#pragma unroll
        for (int j = 0; j < 8; j++) acc[i][j] = 0.f;

    const int arow = tid >> 1;
    const int akk  = (tid & 1) * 4;
    const float* Aptr = A + (size_t)(bm + arow) * K + akk;
    const float* Bptr = B + (size_t)(bn + arow) * K + akk;

    for (int k0 = 0; k0 < K; k0 += 8) {
        float4 av = *(const float4*)(Aptr + k0);
        float4 bv = *(const float4*)(Bptr + k0);
        __syncthreads();
        As[akk + 0][arow] = av.x; As[akk + 1][arow] = av.y;
        As[akk + 2][arow] = av.z; As[akk + 3][arow] = av.w;
        Bs[akk + 0][arow] = bv.x; Bs[akk + 1][arow] = bv.y;
        Bs[akk + 2][arow] = bv.z; Bs[akk + 3][arow] = bv.w;
        __syncthreads();
#pragma unroll
        for (int k = 0; k < 8; k++) {
            float4 a0 = *(const float4*)&As[k][m0];
            float4 a1 = *(const float4*)&As[k][m0 + 4];
            float4 b0 = *(const float4*)&Bs[k][n0];
            float4 b1 = *(const float4*)&Bs[k][n0 + 4];
            float ra[8] = {a0.x, a0.y, a0.z, a0.w, a1.x, a1.y, a1.z, a1.w};
            float rb[8] = {b0.x, b0.y, b0.z, b0.w, b1.x, b1.y, b1.z, b1.w};
#pragma unroll
            for (int i = 0; i < 8; i++)
#pragma unroll
                for (int j = 0; j < 8; j++)
                    acc[i][j] = fmaf(ra[i], rb[j], acc[i][j]);
        }
    }

#pragma unroll
    for (int i = 0; i < 8; i++) {
        const int row = bm + m0 + i;
#pragma unroll
        for (int j = 0; j < 8; j++)
            C[(size_t)row * N + bn + n0 + j] = acc[i][j] + bias[bn + n0 + j];
    }
}

// ---------------- shared device helpers ----------------
// packed f32x2 FMA: d = a*b + c elementwise on {lo,hi} float pairs
__device__ __forceinline__ void fma2(unsigned long long& d,
                                     unsigned long long a,
                                     unsigned long long b,
                                     unsigned long long c)
{
    asm("fma.rn.f32x2 %0, %1, %2, %3;" : "=l"(d) : "l"(a), "l"(b), "l"(c));
}

// load 3 weight rows (j, H+j, 2H+j) as packed f32x2 pairs, 12 pairs per gate
__device__ __forceinline__ void load_wregs_p(const float* __restrict__ W, int j,
                                             int lane, unsigned long long* w0,
                                             unsigned long long* w1,
                                             unsigned long long* w2)
{
#pragma unroll
    for (int k6 = 0; k6 < 6; k6++) {
        const int c = k6 * 128 + lane * 4;   // 16B aligned
        ulonglong2 q0 = *(const ulonglong2*)(W + (size_t)(0 * H + j) * H + c);
        ulonglong2 q1 = *(const ulonglong2*)(W + (size_t)(1 * H + j) * H + c);
        ulonglong2 q2 = *(const ulonglong2*)(W + (size_t)(2 * H + j) * H + c);
        w0[k6*2+0] = q0.x; w0[k6*2+1] = q0.y;
        w1[k6*2+0] = q1.x; w1[k6*2+1] = q1.y;
        w2[k6*2+0] = q2.x; w2[k6*2+1] = q2.y;
    }
}

// poll a 768-word canary row into smem; threads 0..383 poll 2 words each
// (parallel, per-word early exit, NO backoff on the hot path — R8 exact).
__device__ __forceinline__ void poll_row(const unsigned* __restrict__ src,
                                         float* __restrict__ dst, int tid,
                                         bool backoff)
{
    if (tid < 384) {
        const int p0 = tid, p1 = tid + 384;
        unsigned v;
        bool d0 = false, d1 = false;
        do {
            if (!d0) {
                asm volatile("ld.relaxed.gpu.global.u32 %0, [%1];" : "=r"(v) : "l"(src + p0));
                if (v != CANARY) { dst[p0] = __uint_as_float(v); d0 = true; }
            }
            if (!d1) {
                asm volatile("ld.relaxed.gpu.global.u32 %0, [%1];" : "=r"(v) : "l"(src + p1));
                if (v != CANARY) { dst[p1] = __uint_as_float(v); d1 = true; }
            }
            if (d0 && d1) break;
            if (backoff) __nanosleep(64);
        } while (true);
    }
}

// 3 packed dot products (12 f32x2 FMAs per gate) + warp reduce; lane0 gets sums
__device__ __forceinline__ void dot3_reduce_p(const unsigned long long* w0,
                                              const unsigned long long* w1,
                                              const unsigned long long* w2,
                                              const unsigned long long* hp,
                                              float& a0, float& a1, float& a2)
{
    unsigned long long A0 = 0ull, A1 = 0ull, A2 = 0ull;  // {0.f, 0.f}
#pragma unroll
    for (int k = 0; k < 12; k++) {
        fma2(A0, w0[k], hp[k], A0);
        fma2(A1, w1[k], hp[k], A1);
        fma2(A2, w2[k], hp[k], A2);
    }
    float lo, hi;
    asm("mov.b64 {%0,%1}, %2;" : "=f"(lo), "=f"(hi) : "l"(A0)); a0 = lo + hi;
    asm("mov.b64 {%0,%1}, %2;" : "=f"(lo), "=f"(hi) : "l"(A1)); a1 = lo + hi;
    asm("mov.b64 {%0,%1}, %2;" : "=f"(lo), "=f"(hi) : "l"(A2)); a2 = lo + hi;
#pragma unroll
    for (int off = 16; off > 0; off >>= 1) {
        a0 += __shfl_down_sync(0xffffffffu, a0, off);
        a1 += __shfl_down_sync(0xffffffffu, a1, off);
        a2 += __shfl_down_sync(0xffffffffu, a2, off);
    }
}

// stage this lane's 12 h pairs from smem (16B-aligned ulonglong2 reads)
__device__ __forceinline__ void load_hpairs(const float* __restrict__ hsrow,
                                            int lane, unsigned long long* hp)
{
#pragma unroll
    for (int k6 = 0; k6 < 6; k6++) {
        ulonglong2 q = *(const ulonglong2*)(hsrow + k6 * 128 + lane * 4);
        hp[k6*2+0] = q.x; hp[k6*2+1] = q.y;
    }
}

// ---------------- paired-layer wavefront kernel -----------------------------
// grid = 144 CTAs x 512 threads = 1 CTA/SM, three 48-CTA roles (R8 topology):
//  A (bid  0..47 ): even-layer scan; gi0 precomputed; publishes h_e rows.
//  G (bid 48..95 ): streams gi1[t] = W_ih1 * h_e[t] + b (pipelines behind A).
//  B (bid 96..143): odd-layer scan; polls gi1 words + own h_o peers.
__global__ void __launch_bounds__(THR, 1) gru_pair_kernel(
    const float* __restrict__ gi0,
    const float* __restrict__ whh_e, const float* __restrict__ bhh_e,
    const float* __restrict__ wih_o, const float* __restrict__ bih_o,
    const float* __restrict__ whh_o, const float* __restrict__ bhh_o,
    float* __restrict__ h_e, float* __restrict__ h_o)
{
    __shared__ float hs[2][H];
    const int bid  = blockIdx.x;
    const int tid  = threadIdx.x;
    const int warp = tid >> 5;
    const int lane = tid & 31;

    if (bid < NBR) {
        // -------- role A: even-layer scan --------
        const int j = bid * NW + warp;
        unsigned long long w0[12], w1[12], w2[12];
        load_wregs_p(whh_e, j, lane, w0, w1, w2);
        const float b0 = bhh_e[j], b1 = bhh_e[H + j], b2 = bhh_e[2 * H + j];

        for (int t = 0; t < T_SEQ; t++) {
            float gir = 0.f, giz = 0.f, gin = 0.f;
            if (lane == 0) {
                const float* g = gi0 + (size_t)t * H3;
                gir = g[j]; giz = g[H + j]; gin = g[2 * H + j];
            }
            unsigned long long hp[12];
            float hprev = 0.f;
            if (t == 0) {
#pragma unroll
                for (int k = 0; k < 12; k++) hp[k] = 0ull;
            } else {
                const int rb = (t - 1) & 1;
                poll_row((const unsigned*)(h_e + (size_t)(t - 1) * H),
                         hs[rb], tid, false);
                __syncthreads();
                load_hpairs(hs[rb], lane, hp);
                if (lane == 0) hprev = hs[rb][j];
            }
            float a0, a1, a2;
            dot3_reduce_p(w0, w1, w2, hp, a0, a1, a2);
            if (lane == 0) {
                const float r = 1.f / (1.f + __expf(-(gir + a0 + b0)));
                const float z = 1.f / (1.f + __expf(-(giz + a1 + b1)));
                const float n = tanhf(fmaf(r, a2 + b2, gin));
                const float hnew = (1.f - z) * n + z * hprev;
                asm volatile("st.relaxed.gpu.global.u32 [%0], %1;"
                             :: "l"(h_e + (size_t)t * H + j),
                                "r"(__float_as_uint(hnew)) : "memory");
            }
        }
    } else if (bid < 2 * NBR) {
        // -------- role G: gi streamer --------
        const int j = (bid - NBR) * NW + warp;
        unsigned long long w0[12], w1[12], w2[12];
        load_wregs_p(wih_o, j, lane, w0, w1, w2);
        const float b0 = bih_o[j], b1 = bih_o[H + j], b2 = bih_o[2 * H + j];

        for (int t = 0; t < T_SEQ; t++) {
            const int p = t & 1;
            poll_row((const unsigned*)(h_e + (size_t)t * H), hs[p], tid, true);
            __syncthreads();
            unsigned long long xp[12];
            load_hpairs(hs[p], lane, xp);
            float a0, a1, a2;
            dot3_reduce_p(w0, w1, w2, xp, a0, a1, a2);
            if (lane == 0) {
                float* g = g_gi1 + (size_t)t * H3;
                asm volatile("st.relaxed.gpu.global.u32 [%0], %1;"
                             :: "l"(g + j), "r"(__float_as_uint(a0 + b0)) : "memory");
                asm volatile("st.relaxed.gpu.global.u32 [%0], %1;"
                             :: "l"(g + H + j), "r"(__float_as_uint(a1 + b1)) : "memory");
                asm volatile("st.relaxed.gpu.global.u32 [%0], %1;"
                             :: "l"(g + 2 * H + j), "r"(__float_as_uint(a2 + b2)) : "memory");
            }
        }
    } else {
        // -------- role B: odd-layer scan --------
        const int j = (bid - 2 * NBR) * NW + warp;
        unsigned long long w0[12], w1[12], w2[12];
        load_wregs_p(whh_o, j, lane, w0, w1, w2);
        const float b0 = bhh_o[j], b1 = bhh_o[H + j], b2 = bhh_o[2 * H + j];

        for (int t = 0; t < T_SEQ; t++) {
            float gir = 0.f, giz = 0.f, gin = 0.f;
            if (lane == 0) {
                const unsigned* g = (const unsigned*)(g_gi1 + (size_t)t * H3);
                unsigned v;
                bool d0 = false, d1 = false, d2 = false;
                do {
                    if (!d0) {
                        asm volatile("ld.relaxed.gpu.global.u32 %0, [%1];"
                                     : "=r"(v) : "l"(g + j));
                        if (v != CANARY) { gir = __uint_as_float(v); d0 = true; }
                    }
                    if (!d1) {
                        asm volatile("ld.relaxed.gpu.global.u32 %0, [%1];"
                                     : "=r"(v) : "l"(g + H + j));
                        if (v != CANARY) { giz = __uint_as_float(v); d1 = true; }
                    }
                    if (!d2) {
                        asm volatile("ld.relaxed.gpu.global.u32 %0, [%1];"
                                     : "=r"(v) : "l"(g + 2 * H + j));
                        if (v != CANARY) { gin = __uint_as_float(v); d2 = true; }
                    }
                    if (d0 && d1 && d2) break;
                    __nanosleep(64);
                } while (true);
            }
            unsigned long long hp[12];
            float hprev = 0.f;
            if (t == 0) {
#pragma unroll
                for (int k = 0; k < 12; k++) hp[k] = 0ull;
            } else {
                const int rb = (t - 1) & 1;
                poll_row((const unsigned*)(h_o + (size_t)(t - 1) * H),
                         hs[rb], tid, false);
                __syncthreads();
                load_hpairs(hs[rb], lane, hp);
                if (lane == 0) hprev = hs[rb][j];
            }
            float a0, a1, a2;
            dot3_reduce_p(w0, w1, w2, hp, a0, a1, a2);
            if (lane == 0) {
                const float r = 1.f / (1.f + __expf(-(gir + a0 + b0)));
                const float z = 1.f / (1.f + __expf(-(giz + a1 + b1)));
                const float n = tanhf(fmaf(r, a2 + b2, gin));
                const float hnew = (1.f - z) * n + z * hprev;
                asm volatile("st.relaxed.gpu.global.u32 [%0], %1;"
                             :: "l"(h_o + (size_t)t * H + j),
                                "r"(__float_as_uint(hnew)) : "memory");
            }
        }
    }
}

// ---------------- launch ----------------
extern "C" void kernel_launch(void* const* d_in, const int* in_sizes, int n_in,
                              void* d_out, int out_size)
{
    const float* x    = (const float*)d_in[0];
    const float* wih0 = (const float*)d_in[1];
    const float* whh0 = (const float*)d_in[2];
    const float* bih0 = (const float*)d_in[3];
    const float* bhh0 = (const float*)d_in[4];
    const float* wih  = (const float*)d_in[5];
    const float* whh  = (const float*)d_in[6];
    const float* bih  = (const float*)d_in[7];
    const float* bhh  = (const float*)d_in[8];
    const float* fcw  = (const float*)d_in[9];
    const float* fcb  = (const float*)d_in[10];

    float *gi0, *hl;
    cudaGetSymbolAddress((void**)&gi0, g_gi0);
    cudaGetSymbolAddress((void**)&hl,  g_hl);

    reset_h_kernel<<<1024, 256>>>();

    const float* cur = x;
    for (int k = 0; k < NL / 2; k++) {
        const int le = 2 * k;
        const int lo = 2 * k + 1;

        const float* wih_e = (le == 0) ? wih0 : wih + (size_t)(le - 1) * H3 * H;
        const float* bih_e = (le == 0) ? bih0 : bih + (size_t)(le - 1) * H3;
        const float* whh_e = (le == 0) ? whh0 : whh + (size_t)(le - 1) * H3 * H;
        const float* bhh_e = (le == 0) ? bhh0 : bhh + (size_t)(le - 1) * H3;
        const float* wih_o = wih + (size_t)(lo - 1) * H3 * H;
        const float* bih_o = bih + (size_t)(lo - 1) * H3;
        const float* whh_o = whh + (size_t)(lo - 1) * H3 * H;
        const float* bhh_o = bhh + (size_t)(lo - 1) * H3;
        const int K = (le == 0) ? NIN : H;

        dim3 grid_gi(H3 / 128, T_SEQ / 128);
        gemm_nt_bias_kernel<<<grid_gi, 256>>>(cur, wih_e, bih_e, gi0,
                                              T_SEQ, H3, K);

        reset_gi1_kernel<<<512, 256>>>();

        float* h_e = hl + (size_t)le * T_SEQ * H;
        float* h_o = hl + (size_t)lo * T_SEQ * H;
        gru_pair_kernel<<<3 * NBR, THR>>>(gi0, whh_e, bhh_e,
                                          wih_o, bih_o, whh_o, bhh_o,
                                          h_e, h_o);
        cur = h_o;
    }

    dim3 grid_fc(NOUT / 128, T_SEQ / 128);
    gemm_nt_bias_kernel<<<grid_fc, 256>>>(cur, fcw, fcb, (float*)d_out,
                                          T_SEQ, NOUT, H);
}

// round 14
// speedup vs baseline: 1.2832x; 1.2832x over previous
#include <cuda_runtime.h>
#include <math.h>

#define T_SEQ 2048
#define H     768
#define H3    2304
#define NL    10
#define NIN   384
#define NOUT  384

#define NBR 48                // CTAs per role (3 roles -> 144 CTAs, 1/SM)
#define NW  16                // warps (h elements) per CTA
#define THR 512
#define CANARY 0x7FC0DEADu    // quiet-NaN payload; unreachable by GRU math

// ---------------- scratch (no allocation allowed) ----------------
__device__ float g_gi0[T_SEQ * H3];     // even-layer gi (GEMM output, plain)
__device__ float g_gi1[T_SEQ * H3];     // odd-layer gi (streamed, canary)
__device__ float g_hl[NL][T_SEQ][H];    // per-layer h outputs (canary)

__global__ void reset_h_kernel() {
    unsigned* p = (unsigned*)g_hl;
    const size_t n = (size_t)NL * T_SEQ * H;
    for (size_t i = blockIdx.x * blockDim.x + threadIdx.x; i < n;
         i += (size_t)gridDim.x * blockDim.x)
        p[i] = CANARY;
}
__global__ void reset_gi1_kernel() {
    unsigned* p = (unsigned*)g_gi1;
    const size_t n = (size_t)T_SEQ * H3;
    for (size_t i = blockIdx.x * blockDim.x + threadIdx.x; i < n;
         i += (size_t)gridDim.x * blockDim.x)
        p[i] = CANARY;
}

// ---------------- GEMM: C[M,N] = A[M,K] * B[N,K]^T + bias[N] ----------------
__global__ void __launch_bounds__(256) gemm_nt_bias_kernel(
    const float* __restrict__ A, const float* __restrict__ B,
    const float* __restrict__ bias, float* __restrict__ C,
    int M, int N, int K)
{
    __shared__ float As[8][128];
    __shared__ float Bs[8][132];

    const int tid = threadIdx.x;
    const int bm = blockIdx.y * 128;
    const int bn = blockIdx.x * 128;
    const int m0 = (tid >> 4) * 8;
    const int n0 = (tid & 15) * 8;

    float acc[8][8];
#pragma unroll
    for (int i = 0; i < 8; i++)
#pragma unroll
        for (int j = 0; j < 8; j++) acc[i][j] = 0.f;

    const int arow = tid >> 1;
    const int akk  = (tid & 1) * 4;
    const float* Aptr = A + (size_t)(bm + arow) * K + akk;
    const float* Bptr = B + (size_t)(bn + arow) * K + akk;

    for (int k0 = 0; k0 < K; k0 += 8) {
        float4 av = *(const float4*)(Aptr + k0);
        float4 bv = *(const float4*)(Bptr + k0);
        __syncthreads();
        As[akk + 0][arow] = av.x; As[akk + 1][arow] = av.y;
        As[akk + 2][arow] = av.z; As[akk + 3][arow] = av.w;
        Bs[akk + 0][arow] = bv.x; Bs[akk + 1][arow] = bv.y;
        Bs[akk + 2][arow] = bv.z; Bs[akk + 3][arow] = bv.w;
        __syncthreads();
#pragma unroll
        for (int k = 0; k < 8; k++) {
            float4 a0 = *(const float4*)&As[k][m0];
            float4 a1 = *(const float4*)&As[k][m0 + 4];
            float4 b0 = *(const float4*)&Bs[k][n0];
            float4 b1 = *(const float4*)&Bs[k][n0 + 4];
            float ra[8] = {a0.x, a0.y, a0.z, a0.w, a1.x, a1.y, a1.z, a1.w};
            float rb[8] = {b0.x, b0.y, b0.z, b0.w, b1.x, b1.y, b1.z, b1.w};
#pragma unroll
            for (int i = 0; i < 8; i++)
#pragma unroll
                for (int j = 0; j < 8; j++)
                    acc[i][j] = fmaf(ra[i], rb[j], acc[i][j]);
        }
    }

#pragma unroll
    for (int i = 0; i < 8; i++) {
        const int row = bm + m0 + i;
#pragma unroll
        for (int j = 0; j < 8; j++)
            C[(size_t)row * N + bn + n0 + j] = acc[i][j] + bias[bn + n0 + j];
    }
}

// ---------------- shared device helpers ----------------
__device__ __forceinline__ void load_wregs(const float* __restrict__ W, int j,
                                           int lane, float* w0, float* w1,
                                           float* w2)
{
#pragma unroll
    for (int k6 = 0; k6 < 6; k6++) {
        const int c = k6 * 128 + lane * 4;
        float4 v0 = *(const float4*)(W + (size_t)(0 * H + j) * H + c);
        float4 v1 = *(const float4*)(W + (size_t)(1 * H + j) * H + c);
        float4 v2 = *(const float4*)(W + (size_t)(2 * H + j) * H + c);
        w0[k6*4+0] = v0.x; w0[k6*4+1] = v0.y; w0[k6*4+2] = v0.z; w0[k6*4+3] = v0.w;
        w1[k6*4+0] = v1.x; w1[k6*4+1] = v1.y; w1[k6*4+2] = v1.z; w1[k6*4+3] = v1.w;
        w2[k6*4+0] = v2.x; w2[k6*4+1] = v2.y; w2[k6*4+2] = v2.z; w2[k6*4+3] = v2.w;
    }
}

// poll a 768-word canary row into smem; threads 0..383 poll 2 words each
// (parallel, per-word early exit).
__device__ __forceinline__ void poll_row(const unsigned* __restrict__ src,
                                         float* __restrict__ dst, int tid,
                                         bool backoff)
{
    if (tid < 384) {
        const int p0 = tid, p1 = tid + 384;
        unsigned v;
        bool d0 = false, d1 = false;
        do {
            if (!d0) {
                asm volatile("ld.relaxed.gpu.global.u32 %0, [%1];" : "=r"(v) : "l"(src + p0));
                if (v != CANARY) { dst[p0] = __uint_as_float(v); d0 = true; }
            }
            if (!d1) {
                asm volatile("ld.relaxed.gpu.global.u32 %0, [%1];" : "=r"(v) : "l"(src + p1));
                if (v != CANARY) { dst[p1] = __uint_as_float(v); d1 = true; }
            }
            if (d0 && d1) break;
            if (backoff) __nanosleep(64);
        } while (true);
    }
}

__device__ __forceinline__ void dot3_reduce(const float* w0, const float* w1,
                                            const float* w2, const float* hv,
                                            float& a0, float& a1, float& a2)
{
    a0 = 0.f; a1 = 0.f; a2 = 0.f;
#pragma unroll
    for (int k = 0; k < 24; k++) {
        a0 = fmaf(w0[k], hv[k], a0);
        a1 = fmaf(w1[k], hv[k], a1);
        a2 = fmaf(w2[k], hv[k], a2);
    }
#pragma unroll
    for (int off = 16; off > 0; off >>= 1) {
        a0 += __shfl_down_sync(0xffffffffu, a0, off);
        a1 += __shfl_down_sync(0xffffffffu, a1, off);
        a2 += __shfl_down_sync(0xffffffffu, a2, off);
    }
}

// ---------------- paired-layer wavefront kernel -----------------------------
// grid = 144 CTAs x 512 threads = 1 CTA/SM, three 48-CTA roles:
//  A (bid  0..47 ): even-layer scan; gi0 precomputed; publishes h_e rows.
//  G (bid 48..95 ): streams gi1[t] = W_ih1 * h_e[t] + b (pipelines behind A).
//  B (bid 96..143): odd-layer scan; polls gi1 words + own h_o peers.
__global__ void __launch_bounds__(THR, 1) gru_pair_kernel(
    const float* __restrict__ gi0,
    const float* __restrict__ whh_e, const float* __restrict__ bhh_e,
    const float* __restrict__ wih_o, const float* __restrict__ bih_o,
    const float* __restrict__ whh_o, const float* __restrict__ bhh_o,
    float* __restrict__ h_e, float* __restrict__ h_o)
{
    __shared__ float hs[2][H];
    const int bid  = blockIdx.x;
    const int tid  = threadIdx.x;
    const int warp = tid >> 5;
    const int lane = tid & 31;

    if (bid < NBR) {
        // -------- role A: even-layer scan --------
        const int j = bid * NW + warp;
        float w0[24], w1[24], w2[24];
        load_wregs(whh_e, j, lane, w0, w1, w2);
        const float b0 = bhh_e[j], b1 = bhh_e[H + j], b2 = bhh_e[2 * H + j];

        for (int t = 0; t < T_SEQ; t++) {
            float gir = 0.f, giz = 0.f, gin = 0.f;
            if (lane == 0) {
                const float* g = gi0 + (size_t)t * H3;
                gir = g[j]; giz = g[H + j]; gin = g[2 * H + j];
            }
            float hv[24];
            float hprev = 0.f;
            if (t == 0) {
#pragma unroll
                for (int k = 0; k < 24; k++) hv[k] = 0.f;
            } else {
                const int rb = (t - 1) & 1;
                poll_row((const unsigned*)(h_e + (size_t)(t - 1) * H),
                         hs[rb], tid, false);
                __syncthreads();
#pragma unroll
                for (int k6 = 0; k6 < 6; k6++) {
                    float4 v = *(const float4*)(&hs[rb][k6 * 128 + lane * 4]);
                    hv[k6*4+0] = v.x; hv[k6*4+1] = v.y;
                    hv[k6*4+2] = v.z; hv[k6*4+3] = v.w;
                }
                if (lane == 0) hprev = hs[rb][j];
            }
            float a0, a1, a2;
            dot3_reduce(w0, w1, w2, hv, a0, a1, a2);
            if (lane == 0) {
                const float r = 1.f / (1.f + __expf(-(gir + a0 + b0)));
                const float z = 1.f / (1.f + __expf(-(giz + a1 + b1)));
                const float n = tanhf(fmaf(r, a2 + b2, gin));
                const float hnew = (1.f - z) * n + z * hprev;
                asm volatile("st.relaxed.gpu.global.u32 [%0], %1;"
                             :: "l"(h_e + (size_t)t * H + j),
                                "r"(__float_as_uint(hnew)) : "memory");
            }
        }
    } else if (bid < 2 * NBR) {
        // -------- role G: gi streamer --------
        const int j = (bid - NBR) * NW + warp;
        float w0[24], w1[24], w2[24];
        load_wregs(wih_o, j, lane, w0, w1, w2);
        const float b0 = bih_o[j], b1 = bih_o[H + j], b2 = bih_o[2 * H + j];

        for (int t = 0; t < T_SEQ; t++) {
            const int p = t & 1;
            poll_row((const unsigned*)(h_e + (size_t)t * H), hs[p], tid, true);
            __syncthreads();
            float xv[24];
#pragma unroll
            for (int k6 = 0; k6 < 6; k6++) {
                float4 v = *(const float4*)(&hs[p][k6 * 128 + lane * 4]);
                xv[k6*4+0] = v.x; xv[k6*4+1] = v.y;
                xv[k6*4+2] = v.z; xv[k6*4+3] = v.w;
            }
            float a0, a1, a2;
            dot3_reduce(w0, w1, w2, xv, a0, a1, a2);
            if (lane == 0) {
                float* g = g_gi1 + (size_t)t * H3;
                asm volatile("st.relaxed.gpu.global.u32 [%0], %1;"
                             :: "l"(g + j), "r"(__float_as_uint(a0 + b0)) : "memory");
                asm volatile("st.relaxed.gpu.global.u32 [%0], %1;"
                             :: "l"(g + H + j), "r"(__float_as_uint(a1 + b1)) : "memory");
                asm volatile("st.relaxed.gpu.global.u32 [%0], %1;"
                             :: "l"(g + 2 * H + j), "r"(__float_as_uint(a2 + b2)) : "memory");
            }
        }
    } else {
        // -------- role B: odd-layer scan --------
        const int j = (bid - 2 * NBR) * NW + warp;
        float w0[24], w1[24], w2[24];
        load_wregs(whh_o, j, lane, w0, w1, w2);
        const float b0 = bhh_o[j], b1 = bhh_o[H + j], b2 = bhh_o[2 * H + j];

        for (int t = 0; t < T_SEQ; t++) {
            float gir = 0.f, giz = 0.f, gin = 0.f;
            if (lane == 0) {
                const unsigned* g = (const unsigned*)(g_gi1 + (size_t)t * H3);
                unsigned v;
                bool d0 = false, d1 = false, d2 = false;
                do {
                    if (!d0) {
                        asm volatile("ld.relaxed.gpu.global.u32 %0, [%1];"
                                     : "=r"(v) : "l"(g + j));
                        if (v != CANARY) { gir = __uint_as_float(v); d0 = true; }
                    }
                    if (!d1) {
                        asm volatile("ld.relaxed.gpu.global.u32 %0, [%1];"
                                     : "=r"(v) : "l"(g + H + j));
                        if (v != CANARY) { giz = __uint_as_float(v); d1 = true; }
                    }
                    if (!d2) {
                        asm volatile("ld.relaxed.gpu.global.u32 %0, [%1];"
                                     : "=r"(v) : "l"(g + 2 * H + j));
                        if (v != CANARY) { gin = __uint_as_float(v); d2 = true; }
                    }
                    if (d0 && d1 && d2) break;
                    __nanosleep(64);
                } while (true);
            }
            float hv[24];
            float hprev = 0.f;
            if (t == 0) {
#pragma unroll
                for (int k = 0; k < 24; k++) hv[k] = 0.f;
            } else {
                const int rb = (t - 1) & 1;
                poll_row((const unsigned*)(h_o + (size_t)(t - 1) * H),
                         hs[rb], tid, false);
                __syncthreads();
#pragma unroll
                for (int k6 = 0; k6 < 6; k6++) {
                    float4 v = *(const float4*)(&hs[rb][k6 * 128 + lane * 4]);
                    hv[k6*4+0] = v.x; hv[k6*4+1] = v.y;
                    hv[k6*4+2] = v.z; hv[k6*4+3] = v.w;
                }
                if (lane == 0) hprev = hs[rb][j];
            }
            float a0, a1, a2;
            dot3_reduce(w0, w1, w2, hv, a0, a1, a2);
            if (lane == 0) {
                const float r = 1.f / (1.f + __expf(-(gir + a0 + b0)));
                const float z = 1.f / (1.f + __expf(-(giz + a1 + b1)));
                const float n = tanhf(fmaf(r, a2 + b2, gin));
                const float hnew = (1.f - z) * n + z * hprev;
                asm volatile("st.relaxed.gpu.global.u32 [%0], %1;"
                             :: "l"(h_o + (size_t)t * H + j),
                                "r"(__float_as_uint(hnew)) : "memory");
            }
        }
    }
}

// ---------------- launch ----------------
extern "C" void kernel_launch(void* const* d_in, const int* in_sizes, int n_in,
                              void* d_out, int out_size)
{
    const float* x    = (const float*)d_in[0];
    const float* wih0 = (const float*)d_in[1];
    const float* whh0 = (const float*)d_in[2];
    const float* bih0 = (const float*)d_in[3];
    const float* bhh0 = (const float*)d_in[4];
    const float* wih  = (const float*)d_in[5];
    const float* whh  = (const float*)d_in[6];
    const float* bih  = (const float*)d_in[7];
    const float* bhh  = (const float*)d_in[8];
    const float* fcw  = (const float*)d_in[9];
    const float* fcb  = (const float*)d_in[10];

    float *gi0, *hl;
    cudaGetSymbolAddress((void**)&gi0, g_gi0);
    cudaGetSymbolAddress((void**)&hl,  g_hl);

    reset_h_kernel<<<1024, 256>>>();

    const float* cur = x;
    for (int k = 0; k < NL / 2; k++) {
        const int le = 2 * k;
        const int lo = 2 * k + 1;

        const float* wih_e = (le == 0) ? wih0 : wih + (size_t)(le - 1) * H3 * H;
        const float* bih_e = (le == 0) ? bih0 : bih + (size_t)(le - 1) * H3;
        const float* whh_e = (le == 0) ? whh0 : whh + (size_t)(le - 1) * H3 * H;
        const float* bhh_e = (le == 0) ? bhh0 : bhh + (size_t)(le - 1) * H3;
        const float* wih_o = wih + (size_t)(lo - 1) * H3 * H;
        const float* bih_o = bih + (size_t)(lo - 1) * H3;
        const float* whh_o = whh + (size_t)(lo - 1) * H3 * H;
        const float* bhh_o = bhh + (size_t)(lo - 1) * H3;
        const int K = (le == 0) ? NIN : H;

        dim3 grid_gi(H3 / 128, T_SEQ / 128);
        gemm_nt_bias_kernel<<<grid_gi, 256>>>(cur, wih_e, bih_e, gi0,
                                              T_SEQ, H3, K);

        reset_gi1_kernel<<<512, 256>>>();

        float* h_e = hl + (size_t)le * T_SEQ * H;
        float* h_o = hl + (size_t)lo * T_SEQ * H;
        gru_pair_kernel<<<3 * NBR, THR>>>(gi0, whh_e, bhh_e,
                                          wih_o, bih_o, whh_o, bhh_o,
                                          h_e, h_o);
        cur = h_o;
    }

    dim3 grid_fc(NOUT / 128, T_SEQ / 128);
    gemm_nt_bias_kernel<<<grid_fc, 256>>>(cur, fcw, fcb, (float*)d_out,
                                          T_SEQ, NOUT, H);
}

// round 15
// speedup vs baseline: 1.3281x; 1.0350x over previous
#include <cuda_runtime.h>
#include <math.h>

#define T_SEQ 2048
#define H     768
#define H3    2304
#define NL    10
#define NIN   384
#define NOUT  384

#define NBR 48                // CTAs per role (3 roles -> 144 CTAs, 1/SM)
#define NW  16                // warps (h elements) per CTA
#define THR 512
#define CANARY 0x7FC0DEADu    // quiet-NaN payload; unreachable by GRU math

// ---------------- scratch (no allocation allowed) ----------------
__device__ float g_gi0[T_SEQ * H3];     // even-layer gi (GEMM output, plain)
__device__ float g_gi1[T_SEQ * H3];     // odd-layer gi (streamed, canary)
__device__ float g_hl[NL][T_SEQ][H];    // per-layer h outputs (canary)

__global__ void reset_h_kernel() {
    unsigned* p = (unsigned*)g_hl;
    const size_t n = (size_t)NL * T_SEQ * H;
    for (size_t i = blockIdx.x * blockDim.x + threadIdx.x; i < n;
         i += (size_t)gridDim.x * blockDim.x)
        p[i] = CANARY;
}
__global__ void reset_gi1_kernel() {
    unsigned* p = (unsigned*)g_gi1;
    const size_t n = (size_t)T_SEQ * H3;
    for (size_t i = blockIdx.x * blockDim.x + threadIdx.x; i < n;
         i += (size_t)gridDim.x * blockDim.x)
        p[i] = CANARY;
}

// ---------------- GEMM: C[M,N] = A[M,K] * B[N,K]^T + bias[N] ----------------
__global__ void __launch_bounds__(256) gemm_nt_bias_kernel(
    const float* __restrict__ A, const float* __restrict__ B,
    const float* __restrict__ bias, float* __restrict__ C,
    int M, int N, int K)
{
    __shared__ float As[8][128];
    __shared__ float Bs[8][132];

    const int tid = threadIdx.x;
    const int bm = blockIdx.y * 128;
    const int bn = blockIdx.x * 128;
    const int m0 = (tid >> 4) * 8;
    const int n0 = (tid & 15) * 8;

    float acc[8][8];
#pragma unroll
    for (int i = 0; i < 8; i++)
#pragma unroll
        for (int j = 0; j < 8; j++) acc[i][j] = 0.f;

    const int arow = tid >> 1;
    const int akk  = (tid & 1) * 4;
    const float* Aptr = A + (size_t)(bm + arow) * K + akk;
    const float* Bptr = B + (size_t)(bn + arow) * K + akk;

    for (int k0 = 0; k0 < K; k0 += 8) {
        float4 av = *(const float4*)(Aptr + k0);
        float4 bv = *(const float4*)(Bptr + k0);
        __syncthreads();
        As[akk + 0][arow] = av.x; As[akk + 1][arow] = av.y;
        As[akk + 2][arow] = av.z; As[akk + 3][arow] = av.w;
        Bs[akk + 0][arow] = bv.x; Bs[akk + 1][arow] = bv.y;
        Bs[akk + 2][arow] = bv.z; Bs[akk + 3][arow] = bv.w;
        __syncthreads();
#pragma unroll
        for (int k = 0; k < 8; k++) {
            float4 a0 = *(const float4*)&As[k][m0];
            float4 a1 = *(const float4*)&As[k][m0 + 4];
            float4 b0 = *(const float4*)&Bs[k][n0];
            float4 b1 = *(const float4*)&Bs[k][n0 + 4];
            float ra[8] = {a0.x, a0.y, a0.z, a0.w, a1.x, a1.y, a1.z, a1.w};
            float rb[8] = {b0.x, b0.y, b0.z, b0.w, b1.x, b1.y, b1.z, b1.w};
#pragma unroll
            for (int i = 0; i < 8; i++)
#pragma unroll
                for (int j = 0; j < 8; j++)
                    acc[i][j] = fmaf(ra[i], rb[j], acc[i][j]);
        }
    }

#pragma unroll
    for (int i = 0; i < 8; i++) {
        const int row = bm + m0 + i;
#pragma unroll
        for (int j = 0; j < 8; j++)
            C[(size_t)row * N + bn + n0 + j] = acc[i][j] + bias[bn + n0 + j];
    }
}

// ---------------- shared device helpers ----------------
__device__ __forceinline__ void load_wregs(const float* __restrict__ W, int j,
                                           int lane, float* w0, float* w1,
                                           float* w2)
{
#pragma unroll
    for (int k6 = 0; k6 < 6; k6++) {
        const int c = k6 * 128 + lane * 4;
        float4 v0 = *(const float4*)(W + (size_t)(0 * H + j) * H + c);
        float4 v1 = *(const float4*)(W + (size_t)(1 * H + j) * H + c);
        float4 v2 = *(const float4*)(W + (size_t)(2 * H + j) * H + c);
        w0[k6*4+0] = v0.x; w0[k6*4+1] = v0.y; w0[k6*4+2] = v0.z; w0[k6*4+3] = v0.w;
        w1[k6*4+0] = v1.x; w1[k6*4+1] = v1.y; w1[k6*4+2] = v1.z; w1[k6*4+3] = v1.w;
        w2[k6*4+0] = v2.x; w2[k6*4+1] = v2.y; w2[k6*4+2] = v2.z; w2[k6*4+3] = v2.w;
    }
}

// poll a 768-word canary row into smem; threads 0..383 poll 2 words each
// (parallel, per-word early exit).
__device__ __forceinline__ void poll_row(const unsigned* __restrict__ src,
                                         float* __restrict__ dst, int tid,
                                         bool backoff)
{
    if (tid < 384) {
        const int p0 = tid, p1 = tid + 384;
        unsigned v;
        bool d0 = false, d1 = false;
        do {
            if (!d0) {
                asm volatile("ld.relaxed.gpu.global.u32 %0, [%1];" : "=r"(v) : "l"(src + p0));
                if (v != CANARY) { dst[p0] = __uint_as_float(v); d0 = true; }
            }
            if (!d1) {
                asm volatile("ld.relaxed.gpu.global.u32 %0, [%1];" : "=r"(v) : "l"(src + p1));
                if (v != CANARY) { dst[p1] = __uint_as_float(v); d1 = true; }
            }
            if (d0 && d1) break;
            if (backoff) __nanosleep(64);
        } while (true);
    }
}

__device__ __forceinline__ void dot3_reduce(const float* w0, const float* w1,
                                            const float* w2, const float* hv,
                                            float& a0, float& a1, float& a2)
{
    a0 = 0.f; a1 = 0.f; a2 = 0.f;
#pragma unroll
    for (int k = 0; k < 24; k++) {
        a0 = fmaf(w0[k], hv[k], a0);
        a1 = fmaf(w1[k], hv[k], a1);
        a2 = fmaf(w2[k], hv[k], a2);
    }
#pragma unroll
    for (int off = 16; off > 0; off >>= 1) {
        a0 += __shfl_down_sync(0xffffffffu, a0, off);
        a1 += __shfl_down_sync(0xffffffffu, a1, off);
        a2 += __shfl_down_sync(0xffffffffu, a2, off);
    }
}

// ---------------- paired-layer wavefront kernel -----------------------------
// grid = 144 CTAs x 512 threads = 1 CTA/SM, three 48-CTA roles:
//  A (bid  0..47 ): even-layer scan; gi0 precomputed; publishes h_e rows.
//  G (bid 48..95 ): streams gi1[t] = W_ih1 * h_e[t] + b (pipelines behind A).
//  B (bid 96..143): odd-layer scan; polls gi1 words + own h_o peers.
__global__ void __launch_bounds__(THR, 1) gru_pair_kernel(
    const float* __restrict__ gi0,
    const float* __restrict__ whh_e, const float* __restrict__ bhh_e,
    const float* __restrict__ wih_o, const float* __restrict__ bih_o,
    const float* __restrict__ whh_o, const float* __restrict__ bhh_o,
    float* __restrict__ h_e, float* __restrict__ h_o)
{
    __shared__ float hs[2][H];
    const int bid  = blockIdx.x;
    const int tid  = threadIdx.x;
    const int warp = tid >> 5;
    const int lane = tid & 31;

    if (bid < NBR) {
        // -------- role A: even-layer scan --------
        const int j = bid * NW + warp;
        float w0[24], w1[24], w2[24];
        load_wregs(whh_e, j, lane, w0, w1, w2);
        const float b0 = bhh_e[j], b1 = bhh_e[H + j], b2 = bhh_e[2 * H + j];

        for (int t = 0; t < T_SEQ; t++) {
            float gir = 0.f, giz = 0.f, gin = 0.f;
            if (lane == 0) {
                const float* g = gi0 + (size_t)t * H3;
                gir = g[j]; giz = g[H + j]; gin = g[2 * H + j];
            }
            float hv[24];
            float hprev = 0.f;
            if (t == 0) {
#pragma unroll
                for (int k = 0; k < 24; k++) hv[k] = 0.f;
            } else {
                const int rb = (t - 1) & 1;
                poll_row((const unsigned*)(h_e + (size_t)(t - 1) * H),
                         hs[rb], tid, false);
                __syncthreads();
#pragma unroll
                for (int k6 = 0; k6 < 6; k6++) {
                    float4 v = *(const float4*)(&hs[rb][k6 * 128 + lane * 4]);
                    hv[k6*4+0] = v.x; hv[k6*4+1] = v.y;
                    hv[k6*4+2] = v.z; hv[k6*4+3] = v.w;
                }
                if (lane == 0) hprev = hs[rb][j];
            }
            float a0, a1, a2;
            dot3_reduce(w0, w1, w2, hv, a0, a1, a2);
            if (lane == 0) {
                const float r = 1.f / (1.f + __expf(-(gir + a0 + b0)));
                const float z = 1.f / (1.f + __expf(-(giz + a1 + b1)));
                const float n = tanhf(fmaf(r, a2 + b2, gin));
                const float hnew = (1.f - z) * n + z * hprev;
                asm volatile("st.relaxed.gpu.global.u32 [%0], %1;"
                             :: "l"(h_e + (size_t)t * H + j),
                                "r"(__float_as_uint(hnew)) : "memory");
            }
        }
    } else if (bid < 2 * NBR) {
        // -------- role G: gi streamer --------
        const int j = (bid - NBR) * NW + warp;
        float w0[24], w1[24], w2[24];
        load_wregs(wih_o, j, lane, w0, w1, w2);
        const float b0 = bih_o[j], b1 = bih_o[H + j], b2 = bih_o[2 * H + j];

        for (int t = 0; t < T_SEQ; t++) {
            const int p = t & 1;
            poll_row((const unsigned*)(h_e + (size_t)t * H), hs[p], tid, true);
            __syncthreads();
            float xv[24];
#pragma unroll
            for (int k6 = 0; k6 < 6; k6++) {
                float4 v = *(const float4*)(&hs[p][k6 * 128 + lane * 4]);
                xv[k6*4+0] = v.x; xv[k6*4+1] = v.y;
                xv[k6*4+2] = v.z; xv[k6*4+3] = v.w;
            }
            float a0, a1, a2;
            dot3_reduce(w0, w1, w2, xv, a0, a1, a2);
            if (lane == 0) {
                float* g = g_gi1 + (size_t)t * H3;
                asm volatile("st.relaxed.gpu.global.u32 [%0], %1;"
                             :: "l"(g + j), "r"(__float_as_uint(a0 + b0)) : "memory");
                asm volatile("st.relaxed.gpu.global.u32 [%0], %1;"
                             :: "l"(g + H + j), "r"(__float_as_uint(a1 + b1)) : "memory");
                asm volatile("st.relaxed.gpu.global.u32 [%0], %1;"
                             :: "l"(g + 2 * H + j), "r"(__float_as_uint(a2 + b2)) : "memory");
            }
        }
    } else {
        // -------- role B: odd-layer scan --------
        const int j = (bid - 2 * NBR) * NW + warp;
        float w0[24], w1[24], w2[24];
        load_wregs(whh_o, j, lane, w0, w1, w2);
        const float b0 = bhh_o[j], b1 = bhh_o[H + j], b2 = bhh_o[2 * H + j];

        for (int t = 0; t < T_SEQ; t++) {
            float gir = 0.f, giz = 0.f, gin = 0.f;
            if (lane == 0) {
                const unsigned* g = (const unsigned*)(g_gi1 + (size_t)t * H3);
                unsigned v;
                bool d0 = false, d1 = false, d2 = false;
                do {
                    if (!d0) {
                        asm volatile("ld.relaxed.gpu.global.u32 %0, [%1];"
                                     : "=r"(v) : "l"(g + j));
                        if (v != CANARY) { gir = __uint_as_float(v); d0 = true; }
                    }
                    if (!d1) {
                        asm volatile("ld.relaxed.gpu.global.u32 %0, [%1];"
                                     : "=r"(v) : "l"(g + H + j));
                        if (v != CANARY) { giz = __uint_as_float(v); d1 = true; }
                    }
                    if (!d2) {
                        asm volatile("ld.relaxed.gpu.global.u32 %0, [%1];"
                                     : "=r"(v) : "l"(g + 2 * H + j));
                        if (v != CANARY) { gin = __uint_as_float(v); d2 = true; }
                    }
                    if (d0 && d1 && d2) break;
                    __nanosleep(64);
                } while (true);
            }
            float hv[24];
            float hprev = 0.f;
            if (t == 0) {
#pragma unroll
                for (int k = 0; k < 24; k++) hv[k] = 0.f;
            } else {
                const int rb = (t - 1) & 1;
                poll_row((const unsigned*)(h_o + (size_t)(t - 1) * H),
                         hs[rb], tid, false);
                __syncthreads();
#pragma unroll
                for (int k6 = 0; k6 < 6; k6++) {
                    float4 v = *(const float4*)(&hs[rb][k6 * 128 + lane * 4]);
                    hv[k6*4+0] = v.x; hv[k6*4+1] = v.y;
                    hv[k6*4+2] = v.z; hv[k6*4+3] = v.w;
                }
                if (lane == 0) hprev = hs[rb][j];
            }
            float a0, a1, a2;
            dot3_reduce(w0, w1, w2, hv, a0, a1, a2);
            if (lane == 0) {
                const float r = 1.f / (1.f + __expf(-(gir + a0 + b0)));
                const float z = 1.f / (1.f + __expf(-(giz + a1 + b1)));
                const float n = tanhf(fmaf(r, a2 + b2, gin));
                const float hnew = (1.f - z) * n + z * hprev;
                asm volatile("st.relaxed.gpu.global.u32 [%0], %1;"
                             :: "l"(h_o + (size_t)t * H + j),
                                "r"(__float_as_uint(hnew)) : "memory");
            }
        }
    }
}

// ---------------- launch ----------------
extern "C" void kernel_launch(void* const* d_in, const int* in_sizes, int n_in,
                              void* d_out, int out_size)
{
    const float* x    = (const float*)d_in[0];
    const float* wih0 = (const float*)d_in[1];
    const float* whh0 = (const float*)d_in[2];
    const float* bih0 = (const float*)d_in[3];
    const float* bhh0 = (const float*)d_in[4];
    const float* wih  = (const float*)d_in[5];
    const float* whh  = (const float*)d_in[6];
    const float* bih  = (const float*)d_in[7];
    const float* bhh  = (const float*)d_in[8];
    const float* fcw  = (const float*)d_in[9];
    const float* fcb  = (const float*)d_in[10];

    float *gi0, *hl;
    cudaGetSymbolAddress((void**)&gi0, g_gi0);
    cudaGetSymbolAddress((void**)&hl,  g_hl);

    reset_h_kernel<<<1024, 256>>>();

    const float* cur = x;
    for (int k = 0; k < NL / 2; k++) {
        const int le = 2 * k;
        const int lo = 2 * k + 1;

        const float* wih_e = (le == 0) ? wih0 : wih + (size_t)(le - 1) * H3 * H;
        const float* bih_e = (le == 0) ? bih0 : bih + (size_t)(le - 1) * H3;
        const float* whh_e = (le == 0) ? whh0 : whh + (size_t)(le - 1) * H3 * H;
        const float* bhh_e = (le == 0) ? bhh0 : bhh + (size_t)(le - 1) * H3;
        const float* wih_o = wih + (size_t)(lo - 1) * H3 * H;
        const float* bih_o = bih + (size_t)(lo - 1) * H3;
        const float* whh_o = whh + (size_t)(lo - 1) * H3 * H;
        const float* bhh_o = bhh + (size_t)(lo - 1) * H3;
        const int K = (le == 0) ? NIN : H;

        dim3 grid_gi(H3 / 128, T_SEQ / 128);
        gemm_nt_bias_kernel<<<grid_gi, 256>>>(cur, wih_e, bih_e, gi0,
                                              T_SEQ, H3, K);

        reset_gi1_kernel<<<512, 256>>>();

        float* h_e = hl + (size_t)le * T_SEQ * H;
        float* h_o = hl + (size_t)lo * T_SEQ * H;
        gru_pair_kernel<<<3 * NBR, THR>>>(gi0, whh_e, bhh_e,
                                          wih_o, bih_o, whh_o, bhh_o,
                                          h_e, h_o);
        cur = h_o;
    }

    dim3 grid_fc(NOUT / 128, T_SEQ / 128);
    gemm_nt_bias_kernel<<<grid_fc, 256>>>(cur, fcw, fcb, (float*)d_out,
                                          T_SEQ, NOUT, H);
}

// round 16
// speedup vs baseline: 1.3492x; 1.0159x over previous
#include <cuda_runtime.h>
#include <math.h>

#define T_SEQ 2048
#define H     768
#define H3    2304
#define NL    10
#define NIN   384
#define NOUT  384

#define NBR 48                // CTAs per role (3 roles -> 144 CTAs, 1/SM)
#define NW  16                // warps (h elements) per CTA
#define THR 512
#define CANARY 0x7FC0DEADu    // quiet-NaN payload; unreachable by GRU math

// ---------------- scratch (no allocation allowed) ----------------
__device__ float g_gi0[T_SEQ * H3];     // even-layer gi (GEMM output, plain)
__device__ float g_gi1[T_SEQ * H3];     // odd-layer gi (streamed, canary)
__device__ float g_hl[NL][T_SEQ][H];    // per-layer h outputs (canary)

__global__ void reset_h_kernel() {
    unsigned* p = (unsigned*)g_hl;
    const size_t n = (size_t)NL * T_SEQ * H;
    for (size_t i = blockIdx.x * blockDim.x + threadIdx.x; i < n;
         i += (size_t)gridDim.x * blockDim.x)
        p[i] = CANARY;
}
__global__ void reset_gi1_kernel() {
    unsigned* p = (unsigned*)g_gi1;
    const size_t n = (size_t)T_SEQ * H3;
    for (size_t i = blockIdx.x * blockDim.x + threadIdx.x; i < n;
         i += (size_t)gridDim.x * blockDim.x)
        p[i] = CANARY;
}

// ---------------- GEMM: C[M,N] = A[M,K] * B[N,K]^T + bias[N] ----------------
__global__ void __launch_bounds__(256) gemm_nt_bias_kernel(
    const float* __restrict__ A, const float* __restrict__ B,
    const float* __restrict__ bias, float* __restrict__ C,
    int M, int N, int K)
{
    __shared__ float As[8][128];
    __shared__ float Bs[8][132];

    const int tid = threadIdx.x;
    const int bm = blockIdx.y * 128;
    const int bn = blockIdx.x * 128;
    const int m0 = (tid >> 4) * 8;
    const int n0 = (tid & 15) * 8;

    float acc[8][8];
#pragma unroll
    for (int i = 0; i < 8; i++)
#pragma unroll
        for (int j = 0; j < 8; j++) acc[i][j] = 0.f;

    const int arow = tid >> 1;
    const int akk  = (tid & 1) * 4;
    const float* Aptr = A + (size_t)(bm + arow) * K + akk;
    const float* Bptr = B + (size_t)(bn + arow) * K + akk;

    for (int k0 = 0; k0 < K; k0 += 8) {
        float4 av = *(const float4*)(Aptr + k0);
        float4 bv = *(const float4*)(Bptr + k0);
        __syncthreads();
        As[akk + 0][arow] = av.x; As[akk + 1][arow] = av.y;
        As[akk + 2][arow] = av.z; As[akk + 3][arow] = av.w;
        Bs[akk + 0][arow] = bv.x; Bs[akk + 1][arow] = bv.y;
        Bs[akk + 2][arow] = bv.z; Bs[akk + 3][arow] = bv.w;
        __syncthreads();
#pragma unroll
        for (int k = 0; k < 8; k++) {
            float4 a0 = *(const float4*)&As[k][m0];
            float4 a1 = *(const float4*)&As[k][m0 + 4];
            float4 b0 = *(const float4*)&Bs[k][n0];
            float4 b1 = *(const float4*)&Bs[k][n0 + 4];
            float ra[8] = {a0.x, a0.y, a0.z, a0.w, a1.x, a1.y, a1.z, a1.w};
            float rb[8] = {b0.x, b0.y, b0.z, b0.w, b1.x, b1.y, b1.z, b1.w};
#pragma unroll
            for (int i = 0; i < 8; i++)
#pragma unroll
                for (int j = 0; j < 8; j++)
                    acc[i][j] = fmaf(ra[i], rb[j], acc[i][j]);
        }
    }

#pragma unroll
    for (int i = 0; i < 8; i++) {
        const int row = bm + m0 + i;
#pragma unroll
        for (int j = 0; j < 8; j++)
            C[(size_t)row * N + bn + n0 + j] = acc[i][j] + bias[bn + n0 + j];
    }
}

// ---------------- shared device helpers ----------------
__device__ __forceinline__ void load_wregs(const float* __restrict__ W, int j,
                                           int lane, float* w0, float* w1,
                                           float* w2)
{
#pragma unroll
    for (int k6 = 0; k6 < 6; k6++) {
        const int c = k6 * 128 + lane * 4;
        float4 v0 = *(const float4*)(W + (size_t)(0 * H + j) * H + c);
        float4 v1 = *(const float4*)(W + (size_t)(1 * H + j) * H + c);
        float4 v2 = *(const float4*)(W + (size_t)(2 * H + j) * H + c);
        w0[k6*4+0] = v0.x; w0[k6*4+1] = v0.y; w0[k6*4+2] = v0.z; w0[k6*4+3] = v0.w;
        w1[k6*4+0] = v1.x; w1[k6*4+1] = v1.y; w1[k6*4+2] = v1.z; w1[k6*4+3] = v1.w;
        w2[k6*4+0] = v2.x; w2[k6*4+1] = v2.y; w2[k6*4+2] = v2.z; w2[k6*4+3] = v2.w;
    }
}

// poll a 768-word canary row into smem; threads 0..383 poll 2 words each
// (parallel, per-word early exit).
__device__ __forceinline__ void poll_row(const unsigned* __restrict__ src,
                                         float* __restrict__ dst, int tid,
                                         bool backoff)
{
    if (tid < 384) {
        const int p0 = tid, p1 = tid + 384;
        unsigned v;
        bool d0 = false, d1 = false;
        do {
            if (!d0) {
                asm volatile("ld.relaxed.gpu.global.u32 %0, [%1];" : "=r"(v) : "l"(src + p0));
                if (v != CANARY) { dst[p0] = __uint_as_float(v); d0 = true; }
            }
            if (!d1) {
                asm volatile("ld.relaxed.gpu.global.u32 %0, [%1];" : "=r"(v) : "l"(src + p1));
                if (v != CANARY) { dst[p1] = __uint_as_float(v); d1 = true; }
            }
            if (d0 && d1) break;
            if (backoff) __nanosleep(64);
        } while (true);
    }
}

__device__ __forceinline__ void dot3_reduce(const float* w0, const float* w1,
                                            const float* w2, const float* hv,
                                            float& a0, float& a1, float& a2)
{
    a0 = 0.f; a1 = 0.f; a2 = 0.f;
#pragma unroll
    for (int k = 0; k < 24; k++) {
        a0 = fmaf(w0[k], hv[k], a0);
        a1 = fmaf(w1[k], hv[k], a1);
        a2 = fmaf(w2[k], hv[k], a2);
    }
#pragma unroll
    for (int off = 16; off > 0; off >>= 1) {
        a0 += __shfl_down_sync(0xffffffffu, a0, off);
        a1 += __shfl_down_sync(0xffffffffu, a1, off);
        a2 += __shfl_down_sync(0xffffffffu, a2, off);
    }
}

// ---------------- paired-layer wavefront kernel -----------------------------
// grid = 144 CTAs x 512 threads = 1 CTA/SM, three 48-CTA roles:
//  A (bid  0..47 ): even-layer scan; gi0 precomputed; publishes h_e rows.
//  G (bid 48..95 ): streams gi1[t] = W_ih1 * h_e[t] + b (pipelines behind A).
//  B (bid 96..143): odd-layer scan; polls gi1 words + own h_o peers.
__global__ void __launch_bounds__(THR, 1) gru_pair_kernel(
    const float* __restrict__ gi0,
    const float* __restrict__ whh_e, const float* __restrict__ bhh_e,
    const float* __restrict__ wih_o, const float* __restrict__ bih_o,
    const float* __restrict__ whh_o, const float* __restrict__ bhh_o,
    float* __restrict__ h_e, float* __restrict__ h_o)
{
    __shared__ float hs[2][H];
    const int bid  = blockIdx.x;
    const int tid  = threadIdx.x;
    const int warp = tid >> 5;
    const int lane = tid & 31;

    if (bid < NBR) {
        // -------- role A: even-layer scan --------
        const int j = bid * NW + warp;
        float w0[24], w1[24], w2[24];
        load_wregs(whh_e, j, lane, w0, w1, w2);
        const float b0 = bhh_e[j], b1 = bhh_e[H + j], b2 = bhh_e[2 * H + j];

        for (int t = 0; t < T_SEQ; t++) {
            float gir = 0.f, giz = 0.f, gin = 0.f;
            if (lane == 0) {
                const float* g = gi0 + (size_t)t * H3;
                gir = g[j]; giz = g[H + j]; gin = g[2 * H + j];
            }
            float hv[24];
            float hprev = 0.f;
            if (t == 0) {
#pragma unroll
                for (int k = 0; k < 24; k++) hv[k] = 0.f;
            } else {
                const int rb = (t - 1) & 1;
                poll_row((const unsigned*)(h_e + (size_t)(t - 1) * H),
                         hs[rb], tid, false);
                __syncthreads();
#pragma unroll
                for (int k6 = 0; k6 < 6; k6++) {
                    float4 v = *(const float4*)(&hs[rb][k6 * 128 + lane * 4]);
                    hv[k6*4+0] = v.x; hv[k6*4+1] = v.y;
                    hv[k6*4+2] = v.z; hv[k6*4+3] = v.w;
                }
                if (lane == 0) hprev = hs[rb][j];
            }
            float a0, a1, a2;
            dot3_reduce(w0, w1, w2, hv, a0, a1, a2);
            if (lane == 0) {
                const float r = 1.f / (1.f + __expf(-(gir + a0 + b0)));
                const float z = 1.f / (1.f + __expf(-(giz + a1 + b1)));
                const float n = tanhf(fmaf(r, a2 + b2, gin));
                const float hnew = (1.f - z) * n + z * hprev;
                asm volatile("st.relaxed.gpu.global.u32 [%0], %1;"
                             :: "l"(h_e + (size_t)t * H + j),
                                "r"(__float_as_uint(hnew)) : "memory");
            }
        }
    } else if (bid < 2 * NBR) {
        // -------- role G: gi streamer --------
        const int j = (bid - NBR) * NW + warp;
        float w0[24], w1[24], w2[24];
        load_wregs(wih_o, j, lane, w0, w1, w2);
        const float b0 = bih_o[j], b1 = bih_o[H + j], b2 = bih_o[2 * H + j];

        for (int t = 0; t < T_SEQ; t++) {
            const int p = t & 1;
            poll_row((const unsigned*)(h_e + (size_t)t * H), hs[p], tid, true);
            __syncthreads();
            float xv[24];
#pragma unroll
            for (int k6 = 0; k6 < 6; k6++) {
                float4 v = *(const float4*)(&hs[p][k6 * 128 + lane * 4]);
                xv[k6*4+0] = v.x; xv[k6*4+1] = v.y;
                xv[k6*4+2] = v.z; xv[k6*4+3] = v.w;
            }
            float a0, a1, a2;
            dot3_reduce(w0, w1, w2, xv, a0, a1, a2);
            if (lane == 0) {
                float* g = g_gi1 + (size_t)t * H3;
                asm volatile("st.relaxed.gpu.global.u32 [%0], %1;"
                             :: "l"(g + j), "r"(__float_as_uint(a0 + b0)) : "memory");
                asm volatile("st.relaxed.gpu.global.u32 [%0], %1;"
                             :: "l"(g + H + j), "r"(__float_as_uint(a1 + b1)) : "memory");
                asm volatile("st.relaxed.gpu.global.u32 [%0], %1;"
                             :: "l"(g + 2 * H + j), "r"(__float_as_uint(a2 + b2)) : "memory");
            }
        }
    } else {
        // -------- role B: odd-layer scan --------
        const int j = (bid - 2 * NBR) * NW + warp;
        float w0[24], w1[24], w2[24];
        load_wregs(whh_o, j, lane, w0, w1, w2);
        const float b0 = bhh_o[j], b1 = bhh_o[H + j], b2 = bhh_o[2 * H + j];

        for (int t = 0; t < T_SEQ; t++) {
            float gir = 0.f, giz = 0.f, gin = 0.f;
            if (lane == 0) {
                const unsigned* g = (const unsigned*)(g_gi1 + (size_t)t * H3);
                unsigned v;
                bool d0 = false, d1 = false, d2 = false;
                do {
                    if (!d0) {
                        asm volatile("ld.relaxed.gpu.global.u32 %0, [%1];"
                                     : "=r"(v) : "l"(g + j));
                        if (v != CANARY) { gir = __uint_as_float(v); d0 = true; }
                    }
                    if (!d1) {
                        asm volatile("ld.relaxed.gpu.global.u32 %0, [%1];"
                                     : "=r"(v) : "l"(g + H + j));
                        if (v != CANARY) { giz = __uint_as_float(v); d1 = true; }
                    }
                    if (!d2) {
                        asm volatile("ld.relaxed.gpu.global.u32 %0, [%1];"
                                     : "=r"(v) : "l"(g + 2 * H + j));
                        if (v != CANARY) { gin = __uint_as_float(v); d2 = true; }
                    }
                    if (d0 && d1 && d2) break;
                    __nanosleep(64);
                } while (true);
            }
            float hv[24];
            float hprev = 0.f;
            if (t == 0) {
#pragma unroll
                for (int k = 0; k < 24; k++) hv[k] = 0.f;
            } else {
                const int rb = (t - 1) & 1;
                poll_row((const unsigned*)(h_o + (size_t)(t - 1) * H),
                         hs[rb], tid, false);
                __syncthreads();
#pragma unroll
                for (int k6 = 0; k6 < 6; k6++) {
                    float4 v = *(const float4*)(&hs[rb][k6 * 128 + lane * 4]);
                    hv[k6*4+0] = v.x; hv[k6*4+1] = v.y;
                    hv[k6*4+2] = v.z; hv[k6*4+3] = v.w;
                }
                if (lane == 0) hprev = hs[rb][j];
            }
            float a0, a1, a2;
            dot3_reduce(w0, w1, w2, hv, a0, a1, a2);
            if (lane == 0) {
                const float r = 1.f / (1.f + __expf(-(gir + a0 + b0)));
                const float z = 1.f / (1.f + __expf(-(giz + a1 + b1)));
                const float n = tanhf(fmaf(r, a2 + b2, gin));
                const float hnew = (1.f - z) * n + z * hprev;
                asm volatile("st.relaxed.gpu.global.u32 [%0], %1;"
                             :: "l"(h_o + (size_t)t * H + j),
                                "r"(__float_as_uint(hnew)) : "memory");
            }
        }
    }
}

// ---------------- launch ----------------
extern "C" void kernel_launch(void* const* d_in, const int* in_sizes, int n_in,
                              void* d_out, int out_size)
{
    const float* x    = (const float*)d_in[0];
    const float* wih0 = (const float*)d_in[1];
    const float* whh0 = (const float*)d_in[2];
    const float* bih0 = (const float*)d_in[3];
    const float* bhh0 = (const float*)d_in[4];
    const float* wih  = (const float*)d_in[5];
    const float* whh  = (const float*)d_in[6];
    const float* bih  = (const float*)d_in[7];
    const float* bhh  = (const float*)d_in[8];
    const float* fcw  = (const float*)d_in[9];
    const float* fcb  = (const float*)d_in[10];

    float *gi0, *hl;
    cudaGetSymbolAddress((void**)&gi0, g_gi0);
    cudaGetSymbolAddress((void**)&hl,  g_hl);

    reset_h_kernel<<<1024, 256>>>();

    const float* cur = x;
    for (int k = 0; k < NL / 2; k++) {
        const int le = 2 * k;
        const int lo = 2 * k + 1;

        const float* wih_e = (le == 0) ? wih0 : wih + (size_t)(le - 1) * H3 * H;
        const float* bih_e = (le == 0) ? bih0 : bih + (size_t)(le - 1) * H3;
        const float* whh_e = (le == 0) ? whh0 : whh + (size_t)(le - 1) * H3 * H;
        const float* bhh_e = (le == 0) ? bhh0 : bhh + (size_t)(le - 1) * H3;
        const float* wih_o = wih + (size_t)(lo - 1) * H3 * H;
        const float* bih_o = bih + (size_t)(lo - 1) * H3;
        const float* whh_o = whh + (size_t)(lo - 1) * H3 * H;
        const float* bhh_o = bhh + (size_t)(lo - 1) * H3;
        const int K = (le == 0) ? NIN : H;

        dim3 grid_gi(H3 / 128, T_SEQ / 128);
        gemm_nt_bias_kernel<<<grid_gi, 256>>>(cur, wih_e, bih_e, gi0,
                                              T_SEQ, H3, K);

        reset_gi1_kernel<<<512, 256>>>();

        float* h_e = hl + (size_t)le * T_SEQ * H;
        float* h_o = hl + (size_t)lo * T_SEQ * H;
        gru_pair_kernel<<<3 * NBR, THR>>>(gi0, whh_e, bhh_e,
                                          wih_o, bih_o, whh_o, bhh_o,
                                          h_e, h_o);
        cur = h_o;
    }

    dim3 grid_fc(NOUT / 128, T_SEQ / 128);
    gemm_nt_bias_kernel<<<grid_fc, 256>>>(cur, fcw, fcb, (float*)d_out,
                                          T_SEQ, NOUT, H);
}